// round 9
// baseline (speedup 1.0000x reference)
#include <cuda_runtime.h>
#include <cuda_bf16.h>
#include <math.h>

#define CELLN 14
#define NCLS  80
#define BPC   3
#define FEAT  95            // 80 + 3 + 12
#define CELLS2 196          // 14*14
#define PRED_PER_B 18620    // 196*95
#define CSF   32.0f
#define IMGF  448.0f
#define EPSF  1e-9f
#define INV_PI2_4 0.40528473456935109f
#define MAXB  4096
#define MAXOBJ 32
#define BLKPB 14            // 13 stream blocks + 1 obj block per batch

__device__ float2 g_stats[MAXB * CELLS2];   // per (batch,cell): {class sumsq, conf sumsq}
__device__ float  g_conf[MAXB];             // per-batch conf sumsq (atomic, reset by consumer)
__device__ int    g_done[MAXB];             // per-batch cells-done counter (reset by consumer)
__device__ float  g_batch_loss[MAXB];
__device__ int    g_count = 0;              // final-reduction arrivals (self-reset)

__global__ __launch_bounds__(256)
void yolo_kernel(const float* __restrict__ predicts,
                 const float* __restrict__ labels,
                 const int*   __restrict__ objects_num,
                 float* __restrict__ out, int B, int M)
{
    __shared__ float sred[8];
    __shared__ int   s_flag;

    const int blk  = blockIdx.x;
    const int b    = blk / BLKPB;
    const int r    = blk - b * BLKPB;       // 0..12 stream, 13 obj
    const int tid  = threadIdx.x;
    const int lane = tid & 31;
    const int wid  = tid >> 5;

    if (r < 13) {
        // ================= STREAM BLOCK: 16 cells (8 warps x 2) =============
        const int cl = r * 16 + wid * 2;        // cell within batch
        if (cl < CELLS2) {
            const int cell = b * CELLS2 + cl;
            const float* p0 = predicts + (size_t)cell * FEAT;
            const float* p1 = p0 + FEAT;
            const float a0 = p0[lane], b0 = p0[lane + 32], q0 = (lane < 31) ? p0[lane + 64] : 0.0f;
            const float a1 = p1[lane], b1 = p1[lane + 32], q1 = (lane < 31) ? p1[lane + 64] : 0.0f;

            float cls0 = a0 * a0 + b0 * b0;
            float cls1 = a1 * a1 + b1 * b1;
            float conf0 = 0.f, conf1 = 0.f;
            const float q02 = q0 * q0, q12 = q1 * q1;
            if (lane < 16)      { cls0 += q02;  cls1 += q12; }   // feats 64..79: class
            else if (lane < 19) { conf0 = q02;  conf1 = q12; }   // feats 80..82: conf

            #pragma unroll
            for (int off = 16; off; off >>= 1) {
                cls0  += __shfl_xor_sync(0xFFFFFFFFu, cls0,  off);
                cls1  += __shfl_xor_sync(0xFFFFFFFFu, cls1,  off);
                conf0 += __shfl_xor_sync(0xFFFFFFFFu, conf0, off);
                conf1 += __shfl_xor_sync(0xFFFFFFFFu, conf1, off);
            }
            if (lane == 0) {
                g_stats[cell]     = make_float2(cls0, conf0);
                g_stats[cell + 1] = make_float2(cls1, conf1);
                atomicAdd(&g_conf[b], conf0 + conf1);
            }
        }
        // release: all writes -> bar -> single fence -> arrival
        __syncthreads();
        if (tid == 0) {
            __threadfence();
            const int nc = (r < 12) ? 16 : 4;
            atomicAdd(&g_done[b], nc);
        }
        return;
    }

    // ================= OBJ BLOCK (one per batch) ============================
    if (tid == 0) {
        volatile int* vd = (volatile int*)&g_done[b];
        while (*vd < CELLS2) __nanosleep(64);
        g_done[b] = 0;              // reset for next graph replay
        __threadfence();            // acquire
    }
    __syncthreads();

    int nobj = objects_num[b];
    if (nobj > M) nobj = M;
    if (nobj > MAXOBJ) nobj = MAXOBJ;

    const float*  pb = predicts + (size_t)b * PRED_PER_B;
    const float2* st = g_stats + b * CELLS2;
    const float   S_conf2 = g_conf[b];
    const float*  lb = labels + (size_t)b * M * 5;

    float wacc = 0.0f;
    for (int o = wid; o < nobj; o += 8) {
        const float x = __ldg(lb + o * 5 + 0), y = __ldg(lb + o * 5 + 1);
        const float w = __ldg(lb + o * 5 + 2), h = __ldg(lb + o * 5 + 3);
        const int   k = (int)__ldg(lb + o * 5 + 4);

        int ix0 = (int)floorf((x - 0.5f * w) * (1.0f / CSF));
        int ix1 = (int)fminf(ceilf((x + 0.5f * w) * (1.0f / CSF)), (float)CELLN);
        int iy0 = (int)floorf((y - 0.5f * h) * (1.0f / CSF));
        int iy1 = (int)fminf(ceilf((y + 0.5f * h) * (1.0f / CSF)), (float)CELLN);
        ix0 = max(ix0, 0); iy0 = max(iy0, 0);
        const int nx = max(0, ix1 - ix0);
        const int ny = max(0, iy1 - iy0);
        const int cnt = nx * ny;

        // class loss: sum over mask of (sumsq - 2 p_k + 1); all L2-hot
        float cls = 0.0f;
        for (int t = lane; t < cnt; t += 32) {
            const int iy = iy0 + t / nx;
            const int ix = ix0 + t % nx;
            const int cell = iy * CELLN + ix;
            cls += __ldg(&st[cell].x) - 2.0f * __ldg(pb + cell * FEAT + k) + 1.0f;
        }
        #pragma unroll
        for (int off = 16; off; off >>= 1)
            cls += __shfl_xor_sync(0xFFFFFFFFu, cls, off);

        // center cell
        const int cx = (int)floorf(x * (1.0f / CSF));
        const int cy = (int)floorf(y * (1.0f / CSF));
        const float* pc = pb + (cy * CELLN + cx) * FEAT;

        float ciou = -1e30f;
        float pC = 0.f, px = 0.f, py = 0.f, pw = 0.f, ph = 0.f;
        if (lane < BPC) {
            pC = __ldg(pc + NCLS + lane);
            const float* bx = pc + NCLS + BPC + 4 * lane;
            px = __ldg(bx + 0) * CSF + (float)cx * CSF;
            py = __ldg(bx + 1) * CSF + (float)cy * CSF;
            pw = __ldg(bx + 2) * IMGF;
            ph = __ldg(bx + 3) * IMGF;

            // CIoU exactly per reference (incl. centers-vs-widths enclose quirk)
            const float x11 = px - 0.5f * pw, x12 = px + 0.5f * pw;
            const float y11 = py - 0.5f * ph, y12 = py + 0.5f * ph;
            const float x21 = x - 0.5f * w,   x22 = x + 0.5f * w;
            const float y21 = y - 0.5f * h,   y22 = y + 0.5f * h;
            const float iw = fmaxf(fminf(x12, x22) - fmaxf(x11, x21), 0.0f);
            const float ih = fmaxf(fminf(y12, y22) - fmaxf(y11, y21), 0.0f);
            const float inter = iw * ih;
            const float uni = pw * ph + w * h - inter;
            const float iou = inter / (uni + EPSF);
            const float cd  = (px - x) * (px - x) + (py - y) * (py - y);
            const float el = fminf(px, x), er = fmaxf(pw, w);
            const float et = fminf(py, y), eb = fmaxf(ph, h);
            const float ed = (er - el) * (er - el) + (eb - et) * (eb - et);
            const float da = atanf(w / (h + EPSF)) - atanf(pw / (ph + EPSF));
            const float v  = INV_PI2_4 * da * da;
            const float alpha = v / (1.0f - iou + v + EPSF);
            ciou = iou - cd / (ed + EPSF) - alpha * v;
        }
        float m = ciou;
        m = fmaxf(m, __shfl_xor_sync(0xFFFFFFFFu, m, 1));
        m = fmaxf(m, __shfl_xor_sync(0xFFFFFFFFu, m, 2));

        float contrib = 0.0f;
        if (lane < BPC && ciou >= m) {
            const float d = pC - ciou;
            contrib += 0.5f * d * d;           // object loss
            contrib -= 0.25f * pC * pC;        // removed from noobject term
            const float dx = (px - x) * (1.0f / CSF);
            const float dy = (py - y) * (1.0f / CSF);
            const float swp = sqrtf(fminf(fmaxf(pw, 0.0f), IMGF));
            const float shp = sqrtf(fminf(fmaxf(ph, 0.0f), IMGF));
            const float dw = swp - sqrtf(fabsf(w));
            const float dh = shp - sqrtf(fabsf(h));
            contrib += 5.0f * (0.5f * dx * dx + 0.5f * dy * dy
                               + (0.5f * dw * dw) * (1.0f / IMGF)
                               + (0.5f * dh * dh) * (1.0f / IMGF));
        }
        contrib += __shfl_xor_sync(0xFFFFFFFFu, contrib, 1);
        contrib += __shfl_xor_sync(0xFFFFFFFFu, contrib, 2);

        if (lane == 0)
            wacc += 0.5f * cls + contrib + 0.25f * S_conf2;
    }

    if (lane == 0) sred[wid] = wacc;
    __syncthreads();
    if (tid == 0) {
        float s = 0.0f;
        #pragma unroll
        for (int i = 0; i < 8; i++) s += sred[i];
        g_batch_loss[b] = s;
        g_conf[b] = 0.0f;           // reset for next replay (consumed above)
        __threadfence();
        s_flag = (atomicAdd(&g_count, 1) == B - 1);
    }
    __syncthreads();
    if (!s_flag) return;

    // ---- last obj block: deterministic-order final reduction ----
    if (tid == 0) __threadfence();
    __syncthreads();
    float a = 0.0f;
    for (int i = tid; i < B; i += 256) a += g_batch_loss[i];
    #pragma unroll
    for (int off = 16; off; off >>= 1)
        a += __shfl_xor_sync(0xFFFFFFFFu, a, off);
    if (lane == 0) sred[wid] = a;
    __syncthreads();
    if (tid == 0) {
        float s = 0.0f;
        #pragma unroll
        for (int i = 0; i < 8; i++) s += sred[i];
        out[0] = s / (float)B;
        g_count = 0;                // reset for next replay
    }
}

extern "C" void kernel_launch(void* const* d_in, const int* in_sizes, int n_in,
                              void* d_out, int out_size)
{
    const float* predicts = (const float*)d_in[0];
    const float* labels   = (const float*)d_in[1];
    const int*   objnum   = (const int*)d_in[2];
    float* out = (float*)d_out;

    const int B = in_sizes[2];
    const int M = in_sizes[1] / (B * 5);

    yolo_kernel<<<B * BLKPB, 256>>>(predicts, labels, objnum, out, B, M);
}

// round 10
// speedup vs baseline: 3.3054x; 3.3054x over previous
#include <cuda_runtime.h>
#include <cuda_bf16.h>
#include <math.h>

#define CELLN 14
#define NCLS  80
#define BPC   3
#define FEAT  95            // 80 + 3 + 12
#define CELLS2 196          // 14*14
#define PRED_PER_B 18620    // 196*95
#define CSF   32.0f
#define IMGF  448.0f
#define EPSF  1e-9f
#define INV_PI2_4 0.40528473456935109f   // 4/pi^2
#define MAXB  4096
#define MAXOBJ 32
#define NT    128           // 4 warps per CTA -> all CTAs co-resident (1 wave)

__device__ float g_batch_loss[MAXB];
__device__ int   g_count = 0;

// ---------------------------------------------------------------------------
// One CTA (4 warps, 128 thr) per batch element; the whole grid fits in ONE
// chip wave (1024 CTAs, ~7/SM), so streaming starts everywhere at t=0 and
// per-CTA phase-2 tails overlap across CTAs.
//  Phase 1 : warp-per-cell coalesced stream, 3-cell unroll (9 front-batched
//            LDG); one butterfly shfl + 16 partials to smem (no long chains).
//  Phase 1b: finish per-cell class sumsq from partials (stride-17, no conflicts).
//  Phase 2 : per-object losses from smem (+ L1/L2 p_k gather).
//  Phase 3 : last-finished CTA -> deterministic final reduction.
// ---------------------------------------------------------------------------
__global__ __launch_bounds__(NT)
void yolo_fused_kernel(const float* __restrict__ predicts,
                       const float* __restrict__ labels,
                       const int*   __restrict__ objects_num,
                       float* __restrict__ out, int B, int M)
{
    __shared__ float spart[CELLS2 * 17];   // 16 class-sumsq partials / cell
    __shared__ float scell[CELLS2 * 16];   // features 80..94 / cell
    __shared__ float ssum2[CELLS2];        // class sumsq / cell
    __shared__ float sred[4];
    __shared__ float sS;
    __shared__ int   s_last;

    const int b    = blockIdx.x;
    const int tid  = threadIdx.x;
    const int lane = tid & 31;
    const int wid  = tid >> 5;             // 0..3

    const float* pb = predicts + (size_t)b * PRED_PER_B;

    // ---- Phase 1: 3-cell unrolled stream (cells ≡ wid mod 4) ----
    float conf2 = 0.0f;
    #pragma unroll 1
    for (int c0 = wid; c0 + 8 < CELLS2; c0 += 12) {
        const float* p0 = pb + c0 * FEAT;
        const float* p1 = pb + (c0 + 4) * FEAT;
        const float* p2 = pb + (c0 + 8) * FEAT;
        // 9 independent front-batched LDG
        const float a0 = p0[lane], b0 = p0[lane + 32], q0 = (lane < 31) ? p0[lane + 64] : 0.0f;
        const float a1 = p1[lane], b1 = p1[lane + 32], q1 = (lane < 31) ? p1[lane + 64] : 0.0f;
        const float a2 = p2[lane], b2 = p2[lane + 32], q2 = (lane < 31) ? p2[lane + 64] : 0.0f;

        float s0 = a0 * a0 + b0 * b0;
        float s1 = a1 * a1 + b1 * b1;
        float s2 = a2 * a2 + b2 * b2;
        const float q02 = q0 * q0, q12 = q1 * q1, q22 = q2 * q2;
        if (lane < 16)      { s0 += q02; s1 += q12; s2 += q22; }
        else if (lane < 19) { conf2 += q02 + q12 + q22; }
        if (lane >= 16 && lane < 31) {
            scell[c0 * 16 + (lane - 16)]       = q0;
            scell[(c0 + 4) * 16 + (lane - 16)] = q1;
            scell[(c0 + 8) * 16 + (lane - 16)] = q2;
        }
        s0 += __shfl_xor_sync(0xFFFFFFFFu, s0, 16);
        s1 += __shfl_xor_sync(0xFFFFFFFFu, s1, 16);
        s2 += __shfl_xor_sync(0xFFFFFFFFu, s2, 16);
        if (lane < 16) {
            spart[c0 * 17 + lane]       = s0;
            spart[(c0 + 4) * 17 + lane] = s1;
            spart[(c0 + 8) * 17 + lane] = s2;
        }
    }
    {   // tail: cell 192 + wid
        const int cell = 192 + wid;
        const float* p = pb + cell * FEAT;
        const float a = p[lane], bv = p[lane + 32], q = (lane < 31) ? p[lane + 64] : 0.0f;
        float s = a * a + bv * bv;
        const float q2 = q * q;
        if (lane < 16) s += q2;
        else if (lane < 19) conf2 += q2;
        if (lane >= 16 && lane < 31) scell[cell * 16 + (lane - 16)] = q;
        s += __shfl_xor_sync(0xFFFFFFFFu, s, 16);
        if (lane < 16) spart[cell * 17 + lane] = s;
    }
    #pragma unroll
    for (int off = 16; off; off >>= 1)
        conf2 += __shfl_xor_sync(0xFFFFFFFFu, conf2, off);
    if (lane == 0) sred[wid] = conf2;
    __syncthreads();

    // ---- Phase 1b: finish per-cell class sumsq ----
    for (int i = tid; i < CELLS2; i += NT) {
        const float* sp = spart + i * 17;
        float s = 0.0f;
        #pragma unroll
        for (int j = 0; j < 16; j++) s += sp[j];
        ssum2[i] = s;
    }
    if (tid == 0) sS = sred[0] + sred[1] + sred[2] + sred[3];
    __syncthreads();
    const float S_conf2 = sS;
    __syncthreads();            // sred reused below

    // ---- Phase 2: per-object work ----
    int nobj = objects_num[b];
    if (nobj > M) nobj = M;
    const float* lb = labels + (size_t)b * M * 5;

    float wacc = 0.0f;
    for (int o = wid; o < nobj; o += 4) {
        const float x = lb[o * 5 + 0], y = lb[o * 5 + 1];
        const float w = lb[o * 5 + 2], h = lb[o * 5 + 3];
        const int   k = (int)lb[o * 5 + 4];

        const int ix0 = (int)floorf((x - 0.5f * w) * (1.0f / CSF));
        const int ix1 = (int)fminf(ceilf((x + 0.5f * w) * (1.0f / CSF)), (float)CELLN);
        const int iy0 = (int)floorf((y - 0.5f * h) * (1.0f / CSF));
        const int iy1 = (int)fminf(ceilf((y + 0.5f * h) * (1.0f / CSF)), (float)CELLN);
        const int nx  = max(0, ix1 - ix0);
        const int ny  = max(0, iy1 - iy0);
        const int cnt = nx * ny;

        // class loss over masked cells: ssum2 - 2 p_k + 1 (p_k: L1/L2-hot)
        float cls = 0.0f;
        for (int t = lane; t < cnt; t += 32) {
            const int iy = iy0 + t / nx;
            const int ix = ix0 + t % nx;
            const int cell = iy * CELLN + ix;
            cls += ssum2[cell] - 2.0f * __ldg(pb + cell * FEAT + k) + 1.0f;
        }
        #pragma unroll
        for (int off = 16; off; off >>= 1)
            cls += __shfl_xor_sync(0xFFFFFFFFu, cls, off);

        // center cell (conf + boxes in smem)
        const int cx = (int)floorf(x * (1.0f / CSF));
        const int cy = (int)floorf(y * (1.0f / CSF));
        const float* sc = scell + (cy * CELLN + cx) * 16;

        float ciou = -1e30f;
        float pC = 0.f, px = 0.f, py = 0.f, pw = 0.f, ph = 0.f;
        if (lane < BPC) {
            pC = sc[lane];                          // feats 80..82
            const float* bx = sc + BPC + 4 * lane;  // feats 83..94
            px = bx[0] * CSF + (float)cx * CSF;
            py = bx[1] * CSF + (float)cy * CSF;
            pw = bx[2] * IMGF;
            ph = bx[3] * IMGF;

            // CIoU exactly per reference (incl. centers-vs-widths enclose quirk)
            const float x11 = px - 0.5f * pw, x12 = px + 0.5f * pw;
            const float y11 = py - 0.5f * ph, y12 = py + 0.5f * ph;
            const float x21 = x - 0.5f * w,   x22 = x + 0.5f * w;
            const float y21 = y - 0.5f * h,   y22 = y + 0.5f * h;
            const float iw = fmaxf(fminf(x12, x22) - fmaxf(x11, x21), 0.0f);
            const float ih = fmaxf(fminf(y12, y22) - fmaxf(y11, y21), 0.0f);
            const float inter = iw * ih;
            const float uni = pw * ph + w * h - inter;
            const float iou = inter / (uni + EPSF);
            const float cd  = (px - x) * (px - x) + (py - y) * (py - y);
            const float el = fminf(px, x), er = fmaxf(pw, w);
            const float et = fminf(py, y), eb = fmaxf(ph, h);
            const float ed = (er - el) * (er - el) + (eb - et) * (eb - et);
            const float da = atanf(w / (h + EPSF)) - atanf(pw / (ph + EPSF));
            const float v  = INV_PI2_4 * da * da;
            const float alpha = v / (1.0f - iou + v + EPSF);
            ciou = iou - cd / (ed + EPSF) - alpha * v;
        }
        float m = ciou;
        m = fmaxf(m, __shfl_xor_sync(0xFFFFFFFFu, m, 1));
        m = fmaxf(m, __shfl_xor_sync(0xFFFFFFFFu, m, 2));

        float contrib = 0.0f;
        if (lane < BPC && ciou >= m) {
            const float d = pC - ciou;
            contrib += 0.5f * d * d;           // object loss
            contrib -= 0.25f * pC * pC;        // removed from noobject term
            const float dx = (px - x) * (1.0f / CSF);
            const float dy = (py - y) * (1.0f / CSF);
            const float swp = sqrtf(fminf(fmaxf(pw, 0.0f), IMGF));
            const float shp = sqrtf(fminf(fmaxf(ph, 0.0f), IMGF));
            const float dw = swp - sqrtf(fabsf(w));
            const float dh = shp - sqrtf(fabsf(h));
            contrib += 5.0f * (0.5f * dx * dx + 0.5f * dy * dy
                               + (0.5f * dw * dw) * (1.0f / IMGF)
                               + (0.5f * dh * dh) * (1.0f / IMGF));
        }
        contrib += __shfl_xor_sync(0xFFFFFFFFu, contrib, 1);
        contrib += __shfl_xor_sync(0xFFFFFFFFu, contrib, 2);

        if (lane == 0)
            wacc += 0.5f * cls + contrib + 0.25f * S_conf2;
    }

    if (lane == 0) sred[wid] = wacc;
    __syncthreads();
    if (tid == 0) {
        g_batch_loss[b] = sred[0] + sred[1] + sred[2] + sred[3];
        __threadfence();
        int prev = atomicAdd(&g_count, 1);
        s_last = (prev == B - 1);
    }
    __syncthreads();

    // ---- Phase 3: last finished CTA -> deterministic final reduction ----
    if (s_last) {
        float a = 0.0f;
        for (int i = tid; i < B; i += NT) a += g_batch_loss[i];
        #pragma unroll
        for (int off = 16; off; off >>= 1)
            a += __shfl_xor_sync(0xFFFFFFFFu, a, off);
        if (lane == 0) sred[wid] = a;
        __syncthreads();
        if (tid == 0) {
            out[0] = (sred[0] + sred[1] + sred[2] + sred[3]) / (float)B;
            g_count = 0;           // reset for next graph replay
        }
    }
}

extern "C" void kernel_launch(void* const* d_in, const int* in_sizes, int n_in,
                              void* d_out, int out_size)
{
    const float* predicts = (const float*)d_in[0];
    const float* labels   = (const float*)d_in[1];
    const int*   objnum   = (const int*)d_in[2];
    float* out = (float*)d_out;

    const int B = in_sizes[2];
    const int M = in_sizes[1] / (B * 5);

    yolo_fused_kernel<<<B, NT>>>(predicts, labels, objnum, out, B, M);
}